// round 11
// baseline (speedup 1.0000x reference)
#include <cuda_runtime.h>
#include <cuda_bf16.h>

// GGMLLinear: out[o] = sum_k x[k] * scales[o, k/32] * q[o,k] + bias[o]
// x: [1, 4096] f32, q: [14336, 4096] int32 (int8-range), scales: [14336, 128] f32,
// bias: [14336] f32, out: [1, 14336] f32.
//
// Memory-bound GEMV (235MB q stream). R11: SINGLE-WAVE launch.
// grid=1792 x 64-thread CTAs, __launch_bounds__(64,13): all CTAs resident
// simultaneously (12-13/SM; smem 13x16KB=208KB<=228KB, 72 regs), identical
// work per CTA -> all finish together, no drain tail (R8 lost ~7% to CTA-
// generation quantization; its measured avg was only ~26 warps/SM anyway, so
// steady-state MLP is unchanged). Each CTA: 8 rows, 2 warps x 2 sequential
// passes of the proven R8 2-row mainloop (smem x, unroll 4, strided-scale
// shuffle). x stays in smem (R2/R10 both proved LDG-x dilutes the L1tex
// miss queue).

#define IN_DIM 4096
#define OUT_DIM 14336
#define NB (IN_DIM / 32)          // 128 scale blocks per row
#define ROWS_PER_CTA 8            // 2 warps x 2 passes x 2 rows
#define THREADS 64

__global__ __launch_bounds__(THREADS, 13)
void ggml_q8_gemv(const float* __restrict__ x,
                  const int* __restrict__ q,
                  const float* __restrict__ scales,
                  const float* __restrict__ bias,
                  float* __restrict__ out)
{
    __shared__ float xs[IN_DIM];

    // Stage x (16KB) into shared. 1024 float4 / 64 threads = 16 each.
    {
        const float4* x4 = reinterpret_cast<const float4*>(x);
        float4* xs4 = reinterpret_cast<float4*>(xs);
        #pragma unroll
        for (int i = threadIdx.x; i < IN_DIM / 4; i += THREADS)
            xs4[i] = x4[i];
    }
    __syncthreads();

    const int warp = threadIdx.x >> 5;
    const int lane = threadIdx.x & 31;
    const int wbase = blockIdx.x * ROWS_PER_CTA + warp * 4;  // 4 rows per warp
    const float4* xs4 = reinterpret_cast<const float4*>(xs);
    const int csel = lane >> 3;

    // Two sequential passes of the proven 2-row mainloop.
    #pragma unroll
    for (int pass = 0; pass < 2; ++pass) {
        const int rowA = wbase + pass * 2;
        const int rowB = rowA + 1;

        const int4* qrowA = reinterpret_cast<const int4*>(q + (size_t)rowA * IN_DIM);
        const int4* qrowB = reinterpret_cast<const int4*>(q + (size_t)rowB * IN_DIM);

        // Preload all 128 scales per row, strided: lane L holds scale[L+32*r].
        // Scale for iter it, lane L: scale[4*it + (L>>3)]
        //   = reg (it>>3) of lane ((it&7)*4 + (L>>3)).
        const float* srowA = scales + (size_t)rowA * NB;
        const float* srowB = scales + (size_t)rowB * NB;
        const float a0 = __ldg(&srowA[lane]);
        const float a1 = __ldg(&srowA[lane + 32]);
        const float a2 = __ldg(&srowA[lane + 64]);
        const float a3 = __ldg(&srowA[lane + 96]);
        const float b0 = __ldg(&srowB[lane]);
        const float b1 = __ldg(&srowB[lane + 32]);
        const float b2 = __ldg(&srowB[lane + 64]);
        const float b3 = __ldg(&srowB[lane + 96]);

        float accA = 0.0f;
        float accB = 0.0f;

        // 1024 int4 per row / 32 lanes = 32 steps. idx4 = it*32 + lane.
        #pragma unroll 4
        for (int it = 0; it < 32; ++it) {
            const int idx4 = it * 32 + lane;
            const int4   qa = __ldg(&qrowA[idx4]);
            const int4   qb = __ldg(&qrowB[idx4]);
            const float4 xv = xs4[idx4];
            const int    src = ((it & 7) << 2) + csel;
            const float  sva = (it < 8) ? a0 : (it < 16) ? a1 : (it < 24) ? a2 : a3;
            const float  svb = (it < 8) ? b0 : (it < 16) ? b1 : (it < 24) ? b2 : b3;
            const float  sA = __shfl_sync(0xffffffffu, sva, src);
            const float  sB = __shfl_sync(0xffffffffu, svb, src);

            float dA = xv.x * (float)qa.x;
            dA = fmaf(xv.y, (float)qa.y, dA);
            dA = fmaf(xv.z, (float)qa.z, dA);
            dA = fmaf(xv.w, (float)qa.w, dA);
            accA = fmaf(sA, dA, accA);

            float dB = xv.x * (float)qb.x;
            dB = fmaf(xv.y, (float)qb.y, dB);
            dB = fmaf(xv.z, (float)qb.z, dB);
            dB = fmaf(xv.w, (float)qb.w, dB);
            accB = fmaf(sB, dB, accB);
        }

        // Warp reductions
        #pragma unroll
        for (int off = 16; off > 0; off >>= 1) {
            accA += __shfl_xor_sync(0xffffffffu, accA, off);
            accB += __shfl_xor_sync(0xffffffffu, accB, off);
        }

        if (lane == 0) {
            out[rowA] = accA + __ldg(&bias[rowA]);
            out[rowB] = accB + __ldg(&bias[rowB]);
        }
    }
}

extern "C" void kernel_launch(void* const* d_in, const int* in_sizes, int n_in,
                              void* d_out, int out_size)
{
    const float* x      = (const float*)d_in[0];
    const int*   q      = (const int*)d_in[1];
    const float* scales = (const float*)d_in[2];
    const float* bias   = (const float*)d_in[3];
    float*       out    = (float*)d_out;

    const int grid = OUT_DIM / ROWS_PER_CTA;   // 1792 — all resident, one wave
    ggml_q8_gemv<<<grid, THREADS>>>(x, q, scales, bias, out);
}

// round 12
// speedup vs baseline: 1.4132x; 1.4132x over previous
#include <cuda_runtime.h>
#include <cuda_bf16.h>

// GGMLLinear: out[o] = sum_k x[k] * scales[o, k/32] * q[o,k] + bias[o]
// x: [1, 4096] f32, q: [14336, 4096] int32 (int8-range), scales: [14336, 128] f32,
// bias: [14336] f32, out: [1, 14336] f32.
//
// Memory-bound GEMV (235MB q stream). R12 = R8 (the proven best: 128 thr,
// 2 rows/warp, smem x, unroll 4, strided-scale shuffle, grid=1792) plus:
//  - prefetch the first 4 q-iterations (8 LDG.128, ~2KB/warp) BEFORE the
//    x-staging loop, so each CTA's DRAM stream starts at cycle ~0 and the
//    staging + __syncthreads() bubble is hidden under q latency;
//  - __launch_bounds__(128,7) (cap 72) so the prefetch payload stays live
//    across staging without splitting the mainloop LDG batch.

#define IN_DIM 4096
#define OUT_DIM 14336
#define NB (IN_DIM / 32)          // 128 scale blocks per row
#define ROWS_PER_CTA 8            // 4 warps x 2 rows
#define THREADS 128
#define PF 4                      // prefetched iterations

__global__ __launch_bounds__(THREADS, 7)
void ggml_q8_gemv(const float* __restrict__ x,
                  const int* __restrict__ q,
                  const float* __restrict__ scales,
                  const float* __restrict__ bias,
                  float* __restrict__ out)
{
    __shared__ float xs[IN_DIM];

    const int warp = threadIdx.x >> 5;
    const int lane = threadIdx.x & 31;
    const int rowA = blockIdx.x * ROWS_PER_CTA + warp * 2;   // grid sized exactly
    const int rowB = rowA + 1;

    const int4* qrowA = reinterpret_cast<const int4*>(q + (size_t)rowA * IN_DIM);
    const int4* qrowB = reinterpret_cast<const int4*>(q + (size_t)rowB * IN_DIM);

    // ---- Prefetch first PF iterations of both q streams (DRAM, ~600cyc) ----
    int4 pqa[PF], pqb[PF];
    #pragma unroll
    for (int it = 0; it < PF; ++it) {
        pqa[it] = __ldg(&qrowA[it * 32 + lane]);
        pqb[it] = __ldg(&qrowB[it * 32 + lane]);
    }

    // Scale preloads (L2-resident, strided: lane L holds scale[L + 32*r]).
    // Scale for iter it, lane L: scale[4*it + (L>>3)]
    //   = reg (it>>3) of lane ((it&7)*4 + (L>>3)).
    const float* srowA = scales + (size_t)rowA * NB;
    const float* srowB = scales + (size_t)rowB * NB;
    const float a0 = __ldg(&srowA[lane]);
    const float a1 = __ldg(&srowA[lane + 32]);
    const float a2 = __ldg(&srowA[lane + 64]);
    const float a3 = __ldg(&srowA[lane + 96]);
    const float b0 = __ldg(&srowB[lane]);
    const float b1 = __ldg(&srowB[lane + 32]);
    const float b2 = __ldg(&srowB[lane + 64]);
    const float b3 = __ldg(&srowB[lane + 96]);
    const int csel = lane >> 3;

    // ---- Stage x (16KB) into shared, overlapped with the prefetch latency ----
    {
        const float4* x4 = reinterpret_cast<const float4*>(x);
        float4* xs4 = reinterpret_cast<float4*>(xs);
        #pragma unroll
        for (int i = threadIdx.x; i < IN_DIM / 4; i += THREADS)
            xs4[i] = x4[i];
    }
    __syncthreads();

    const float4* xs4 = reinterpret_cast<const float4*>(xs);

    float accA = 0.0f;
    float accB = 0.0f;

    // ---- Consume prefetched iterations ----
    #pragma unroll
    for (int it = 0; it < PF; ++it) {
        const float4 xv = xs4[it * 32 + lane];
        const int    src = ((it & 7) << 2) + csel;
        const float  sA = __shfl_sync(0xffffffffu, a0, src);
        const float  sB = __shfl_sync(0xffffffffu, b0, src);

        float dA = xv.x * (float)pqa[it].x;
        dA = fmaf(xv.y, (float)pqa[it].y, dA);
        dA = fmaf(xv.z, (float)pqa[it].z, dA);
        dA = fmaf(xv.w, (float)pqa[it].w, dA);
        accA = fmaf(sA, dA, accA);

        float dB = xv.x * (float)pqb[it].x;
        dB = fmaf(xv.y, (float)pqb[it].y, dB);
        dB = fmaf(xv.z, (float)pqb[it].z, dB);
        dB = fmaf(xv.w, (float)pqb[it].w, dB);
        accB = fmaf(sB, dB, accB);
    }

    // ---- Steady-state mainloop (identical to R8) ----
    #pragma unroll 4
    for (int it = PF; it < 32; ++it) {
        const int idx4 = it * 32 + lane;
        const int4   qa = __ldg(&qrowA[idx4]);
        const int4   qb = __ldg(&qrowB[idx4]);
        const float4 xv = xs4[idx4];
        const int    src = ((it & 7) << 2) + csel;
        const float  sva = (it < 8) ? a0 : (it < 16) ? a1 : (it < 24) ? a2 : a3;
        const float  svb = (it < 8) ? b0 : (it < 16) ? b1 : (it < 24) ? b2 : b3;
        const float  sA = __shfl_sync(0xffffffffu, sva, src);
        const float  sB = __shfl_sync(0xffffffffu, svb, src);

        float dA = xv.x * (float)qa.x;
        dA = fmaf(xv.y, (float)qa.y, dA);
        dA = fmaf(xv.z, (float)qa.z, dA);
        dA = fmaf(xv.w, (float)qa.w, dA);
        accA = fmaf(sA, dA, accA);

        float dB = xv.x * (float)qb.x;
        dB = fmaf(xv.y, (float)qb.y, dB);
        dB = fmaf(xv.z, (float)qb.z, dB);
        dB = fmaf(xv.w, (float)qb.w, dB);
        accB = fmaf(sB, dB, accB);
    }

    // Warp reductions
    #pragma unroll
    for (int off = 16; off > 0; off >>= 1) {
        accA += __shfl_xor_sync(0xffffffffu, accA, off);
        accB += __shfl_xor_sync(0xffffffffu, accB, off);
    }

    if (lane == 0) {
        out[rowA] = accA + __ldg(&bias[rowA]);
        out[rowB] = accB + __ldg(&bias[rowB]);
    }
}

extern "C" void kernel_launch(void* const* d_in, const int* in_sizes, int n_in,
                              void* d_out, int out_size)
{
    const float* x      = (const float*)d_in[0];
    const int*   q      = (const int*)d_in[1];
    const float* scales = (const float*)d_in[2];
    const float* bias   = (const float*)d_in[3];
    float*       out    = (float*)d_out;

    const int grid = OUT_DIM / ROWS_PER_CTA;   // 1792
    ggml_q8_gemv<<<grid, THREADS>>>(x, q, scales, bias, out);
}

// round 13
// speedup vs baseline: 1.4224x; 1.0065x over previous
#include <cuda_runtime.h>
#include <cuda_bf16.h>

// GGMLLinear: out[o] = sum_k x[k] * scales[o, k/32] * q[o,k] + bias[o]
// x: [1, 4096] f32, q: [14336, 4096] int32 (int8-range), scales: [14336, 128] f32,
// bias: [14336] f32, out: [1, 14336] f32.
//
// Memory-bound GEMV (235MB q stream). R13 = R8 (proven best: 128 thr, 4 warps
// x 2 rows, smem x, strided-scale shuffle, grid=1792) with ONE change:
// unroll 4 -> 8 and __launch_bounds__(128,5) (102-reg cap). Payload becomes
// 16 LDG.128 batched per warp (64 regs) -> per-SM in-flight bytes +54% at
// -23% warps. The regs->in-flight->DRAM% lever is the only one that has
// moved BW in 12 rounds (32/48/64 regs -> 58/78/82% DRAM).

#define IN_DIM 4096
#define OUT_DIM 14336
#define NB (IN_DIM / 32)          // 128 scale blocks per row
#define ROWS_PER_CTA 8            // 4 warps x 2 rows
#define THREADS 128

__global__ __launch_bounds__(THREADS, 5)
void ggml_q8_gemv(const float* __restrict__ x,
                  const int* __restrict__ q,
                  const float* __restrict__ scales,
                  const float* __restrict__ bias,
                  float* __restrict__ out)
{
    __shared__ float xs[IN_DIM];

    // Stage x (16KB) into shared. 1024 float4 / 128 threads = 8 each.
    {
        const float4* x4 = reinterpret_cast<const float4*>(x);
        float4* xs4 = reinterpret_cast<float4*>(xs);
        #pragma unroll
        for (int i = threadIdx.x; i < IN_DIM / 4; i += THREADS)
            xs4[i] = x4[i];
    }
    __syncthreads();

    const int warp = threadIdx.x >> 5;
    const int lane = threadIdx.x & 31;
    const int rowA = blockIdx.x * ROWS_PER_CTA + warp * 2;   // grid sized exactly
    const int rowB = rowA + 1;

    const int4*   qrowA = reinterpret_cast<const int4*>(q + (size_t)rowA * IN_DIM);
    const int4*   qrowB = reinterpret_cast<const int4*>(q + (size_t)rowB * IN_DIM);
    const float4* xs4   = reinterpret_cast<const float4*>(xs);

    // Preload all 128 scales per row, strided: lane L holds scale[L + 32*r].
    // Scale for iter it, lane L: scale[4*it + (L>>3)]
    //   = reg (it>>3) of lane ((it&7)*4 + (L>>3)).
    const float* srowA = scales + (size_t)rowA * NB;
    const float* srowB = scales + (size_t)rowB * NB;
    const float a0 = __ldg(&srowA[lane]);
    const float a1 = __ldg(&srowA[lane + 32]);
    const float a2 = __ldg(&srowA[lane + 64]);
    const float a3 = __ldg(&srowA[lane + 96]);
    const float b0 = __ldg(&srowB[lane]);
    const float b1 = __ldg(&srowB[lane + 32]);
    const float b2 = __ldg(&srowB[lane + 64]);
    const float b3 = __ldg(&srowB[lane + 96]);
    const int csel = lane >> 3;

    float accA = 0.0f;
    float accB = 0.0f;

    // 1024 int4 per row / 32 lanes = 32 steps. idx4 = it*32 + lane.
    #pragma unroll 8
    for (int it = 0; it < 32; ++it) {
        const int idx4 = it * 32 + lane;
        const int4   qa = __ldg(&qrowA[idx4]);
        const int4   qb = __ldg(&qrowB[idx4]);
        const float4 xv = xs4[idx4];
        const int    src = ((it & 7) << 2) + csel;
        const float  sva = (it < 8) ? a0 : (it < 16) ? a1 : (it < 24) ? a2 : a3;
        const float  svb = (it < 8) ? b0 : (it < 16) ? b1 : (it < 24) ? b2 : b3;
        const float  sA = __shfl_sync(0xffffffffu, sva, src);
        const float  sB = __shfl_sync(0xffffffffu, svb, src);

        float dA = xv.x * (float)qa.x;
        dA = fmaf(xv.y, (float)qa.y, dA);
        dA = fmaf(xv.z, (float)qa.z, dA);
        dA = fmaf(xv.w, (float)qa.w, dA);
        accA = fmaf(sA, dA, accA);

        float dB = xv.x * (float)qb.x;
        dB = fmaf(xv.y, (float)qb.y, dB);
        dB = fmaf(xv.z, (float)qb.z, dB);
        dB = fmaf(xv.w, (float)qb.w, dB);
        accB = fmaf(sB, dB, accB);
    }

    // Warp reductions
    #pragma unroll
    for (int off = 16; off > 0; off >>= 1) {
        accA += __shfl_xor_sync(0xffffffffu, accA, off);
        accB += __shfl_xor_sync(0xffffffffu, accB, off);
    }

    if (lane == 0) {
        out[rowA] = accA + __ldg(&bias[rowA]);
        out[rowB] = accB + __ldg(&bias[rowB]);
    }
}

extern "C" void kernel_launch(void* const* d_in, const int* in_sizes, int n_in,
                              void* d_out, int out_size)
{
    const float* x      = (const float*)d_in[0];
    const int*   q      = (const int*)d_in[1];
    const float* scales = (const float*)d_in[2];
    const float* bias   = (const float*)d_in[3];
    float*       out    = (float*)d_out;

    const int grid = OUT_DIM / ROWS_PER_CTA;   // 1792
    ggml_q8_gemv<<<grid, THREADS>>>(x, q, scales, bias, out);
}